// round 14
// baseline (speedup 1.0000x reference)
#include <cuda_runtime.h>
#include <cuda_fp16.h>
#include <cstdint>

#define S_LEN  2048
#define BATCH  2
#define DMODEL 1024
#define NHEAD  16
#define HDIM   64
#define MROWS  (S_LEN * BATCH)   // 4096
#define RS     (BATCH * DMODEL)  // 2048

// Scratch (allocation-free: __device__ globals)
__device__ __half g_Q[(size_t)MROWS * DMODEL];
__device__ __half g_K[(size_t)MROWS * DMODEL];   // compacted keys
__device__ __half g_V[(size_t)MROWS * DMODEL];   // compacted values
__device__ __half g_Xh[3][(size_t)MROWS * DMODEL];   // xq full; xk/xv compacted
__device__ __half g_Wh[3][(size_t)DMODEL * DMODEL];
__device__ int    g_nv;
__device__ int    g_cidx[S_LEN];

// ---------------------------------------------------------------------------
// helpers
// ---------------------------------------------------------------------------
__device__ __forceinline__ uint32_t packh2(float a, float b) {
    __half2 h = __floats2half2_rn(a, b);
    return *(uint32_t*)&h;
}
__device__ __forceinline__ uint32_t smem_u32(const void* p) {
    uint32_t a;
    asm("{ .reg .u64 t; cvta.to.shared.u64 t, %1; cvt.u32.u64 %0, t; }"
        : "=r"(a) : "l"(p));
    return a;
}
__device__ __forceinline__ void mma16(float c[4], const uint32_t a[4],
                                      uint32_t b0, uint32_t b1) {
    asm volatile(
        "mma.sync.aligned.m16n8k16.row.col.f32.f16.f16.f32 "
        "{%0,%1,%2,%3}, {%4,%5,%6,%7}, {%8,%9}, {%0,%1,%2,%3};\n"
        : "+f"(c[0]), "+f"(c[1]), "+f"(c[2]), "+f"(c[3])
        : "r"(a[0]), "r"(a[1]), "r"(a[2]), "r"(a[3]), "r"(b0), "r"(b1));
}
__device__ __forceinline__ uint32_t ex2h2(uint32_t s) {
    uint32_t r;
    asm("ex2.approx.f16x2 %0, %1;" : "=r"(r) : "r"(s));
    return r;
}
__device__ __forceinline__ uint32_t hmul2u(uint32_t a, uint32_t b) {
    uint32_t r;
    asm("mul.rn.f16x2 %0, %1, %2;" : "=r"(r) : "r"(a), "r"(b));
    return r;
}
#define LDSM4(r, addr) \
    asm volatile("ldmatrix.sync.aligned.m8n8.x4.shared.b16 {%0,%1,%2,%3}, [%4];" \
        : "=r"((r)[0]), "=r"((r)[1]), "=r"((r)[2]), "=r"((r)[3]) : "r"(addr))
#define LDSM4T(r, addr) \
    asm volatile("ldmatrix.sync.aligned.m8n8.x4.trans.shared.b16 {%0,%1,%2,%3}, [%4];" \
        : "=r"((r)[0]), "=r"((r)[1]), "=r"((r)[2]), "=r"((r)[3]) : "r"(addr))
#define CP16(dst, src) \
    asm volatile("cp.async.cg.shared.global [%0], [%1], 16;" :: "r"(dst), "l"(src))
#define CP_COMMIT() asm volatile("cp.async.commit_group;" ::: "memory")
#define CP_WAIT0()  asm volatile("cp.async.wait_group 0;" ::: "memory")
#define CP_WAIT1()  asm volatile("cp.async.wait_group 1;" ::: "memory")

// ---------------------------------------------------------------------------
// Kernel A: mask prefix-scan -> g_cidx, g_nv.  (unchanged)
// ---------------------------------------------------------------------------
__global__ __launch_bounds__(1024)
void scan_mask(const int* __restrict__ mask)
{
    __shared__ int wsum[32];
    const int tid  = threadIdx.x;
    const int lane = tid & 31;
    const int w    = tid >> 5;
    const int e0 = (mask[2 * tid] != 0);
    const int e1 = (mask[2 * tid + 1] != 0);
    const int cnt = e0 + e1;

    int x = cnt;
    #pragma unroll
    for (int o = 1; o < 32; o <<= 1) {
        int y = __shfl_up_sync(0xffffffffu, x, o);
        if (lane >= o) x += y;
    }
    if (lane == 31) wsum[w] = x;
    __syncthreads();
    if (w == 0) {
        int s = wsum[lane];
        #pragma unroll
        for (int o = 1; o < 32; o <<= 1) {
            int y = __shfl_up_sync(0xffffffffu, s, o);
            if (lane >= o) s += y;
        }
        wsum[lane] = s;
    }
    __syncthreads();
    const int incl = x + (w > 0 ? wsum[w - 1] : 0);
    const int excl = incl - cnt;
    if (e0) g_cidx[excl] = 2 * tid;
    if (e1) g_cidx[excl + e0] = 2 * tid + 1;
    if (tid == 1023) g_nv = incl;
}

// ---------------------------------------------------------------------------
// Kernel B: prep (unchanged).
// ---------------------------------------------------------------------------
__global__ __launch_bounds__(256)
void prep(const float* __restrict__ xq, const float* __restrict__ xk,
          const float* __restrict__ xv, const float* __restrict__ w0,
          const float* __restrict__ w1, const float* __restrict__ w2)
{
    const int z = blockIdx.z;
    if (z >= 4) {
        const int p  = blockIdx.x;
        const int nv = g_nv;
        const int nvp = (nv + 127) & ~127;
        if (p >= nvp) return;
        __half* dst = (z == 4 ? g_Xh[1] : g_Xh[2]) + (size_t)p * RS;
        const int i = threadIdx.x * 8;
        if (p < nv) {
            const int s = g_cidx[p];
            const float* src = (z == 4 ? xk : xv) + (size_t)s * RS;
            float4 a = *(const float4*)&src[i];
            float4 b = *(const float4*)&src[i + 4];
            __half2 h0 = __floats2half2_rn(a.x, a.y);
            __half2 h1 = __floats2half2_rn(a.z, a.w);
            __half2 h2 = __floats2half2_rn(b.x, b.y);
            __half2 h3 = __floats2half2_rn(b.z, b.w);
            *(uint4*)&dst[i] = make_uint4(*(uint32_t*)&h0, *(uint32_t*)&h1,
                                          *(uint32_t*)&h2, *(uint32_t*)&h3);
        } else {
            *(uint4*)&dst[i] = make_uint4(0, 0, 0, 0);
        }
        return;
    }
    const float* s; __half* d; size_t n;
    switch (z) {
        case 0: s = xq; d = g_Xh[0]; n = (size_t)MROWS * DMODEL; break;
        case 1: s = w0; d = g_Wh[0]; n = (size_t)DMODEL * DMODEL; break;
        case 2: s = w1; d = g_Wh[1]; n = (size_t)DMODEL * DMODEL; break;
        default: s = w2; d = g_Wh[2]; n = (size_t)DMODEL * DMODEL; break;
    }
    const size_t n4 = n >> 2;
    const size_t stride = (size_t)gridDim.x * blockDim.x;
    for (size_t i = (size_t)blockIdx.x * blockDim.x + threadIdx.x; i < n4;
         i += stride) {
        float4 v = *(const float4*)&s[i * 4];
        __half2 h0 = __floats2half2_rn(v.x, v.y);
        __half2 h1 = __floats2half2_rn(v.z, v.w);
        *(uint2*)&d[i * 4] = make_uint2(*(uint32_t*)&h0, *(uint32_t*)&h1);
    }
}

// ---------------------------------------------------------------------------
// Kernel 1: QKV projection, M-tile 256 (warp tile 64x64, 4M x 2N warps,
//   1 CTA/SM).  B fragments now amortized over 4 m-tiles (was 2): LDSM per
//   HMMA drops 2.0 -> 1.33 wavefronts, barriers per HMMA halve.
// Smem: 3 stages x 30720 B (A 256x32 @ +0, B 128x32 @ +20480).  Dynamic.
// ---------------------------------------------------------------------------
#define PROJ_STAGE 30720
#define PROJ_SMEM  (3 * PROJ_STAGE)   // 92160

__global__ __launch_bounds__(256, 1)
void qkv_proj_h(const float* __restrict__ Bq, const float* __restrict__ Bk,
                const float* __restrict__ Bv)
{
    const int m0 = blockIdx.y * 256;
    if (blockIdx.z != 0) {
        const int nvp = (g_nv + 127) & ~127;
        if (m0 >= 2 * nvp) return;
    }
    const __half* X = g_Xh[blockIdx.z];
    const __half* W = g_Wh[blockIdx.z];
    const float* bias; __half* out; float oscale;
    if (blockIdx.z == 0)      { bias = Bq; out = g_Q; oscale = 0.125f * 1.44269504f; }
    else if (blockIdx.z == 1) { bias = Bk; out = g_K; oscale = 1.0f; }
    else                      { bias = Bv; out = g_V; oscale = 1.0f; }

    extern __shared__ char smem[];
    const uint32_t sb = smem_u32(smem);

    const int tid  = threadIdx.x;
    const int wid  = tid >> 5;
    const int lane = tid & 31;
    const int g    = lane >> 2;
    const int c    = lane & 3;
    const int mm   = lane >> 3;
    const int lr   = lane & 7;
    const int wm   = (wid & 3) * 64;
    const int wn   = (wid >> 2) * 64;
    const int n0   = blockIdx.x * 128;

    const __half* Xg = X + (size_t)m0 * DMODEL;
    const __half* Wg = W + (size_t)n0 * DMODEL;

    const uint32_t aoff = (uint32_t)((wm + (mm & 1) * 8 + lr) * 80 + (mm >> 1) * 16);
    const uint32_t boff = (uint32_t)(20480 + (wn + (mm >> 1) * 8 + lr) * 80 + (mm & 1) * 16);

    float acc[4][8][4];
    #pragma unroll
    for (int mt = 0; mt < 4; mt++)
        #pragma unroll
        for (int nt = 0; nt < 8; nt++)
            #pragma unroll
            for (int e = 0; e < 4; e++) acc[mt][nt][e] = 0.0f;

    // stage issuance: A = 1024 chunks (4/thread), B = 512 chunks (2/thread)
    #define PROJ_STAGE_ISSUE(stagebase, k0)                                       \
        do {                                                                      \
            _Pragma("unroll")                                                     \
            for (int it_ = 0; it_ < 4; it_++) {                                   \
                const int idx_ = tid + it_ * 256;                                 \
                CP16((stagebase) + (uint32_t)((idx_ >> 2) * 80 + (idx_ & 3) * 16),\
                     Xg + (size_t)(idx_ >> 2) * DMODEL + (k0) + (idx_ & 3) * 8);  \
            }                                                                     \
            _Pragma("unroll")                                                     \
            for (int it_ = 0; it_ < 2; it_++) {                                   \
                const int idx_ = tid + it_ * 256;                                 \
                CP16((stagebase) + 20480u +                                       \
                         (uint32_t)((idx_ >> 2) * 80 + (idx_ & 3) * 16),          \
                     Wg + (size_t)(idx_ >> 2) * DMODEL + (k0) + (idx_ & 3) * 8);  \
            }                                                                     \
            CP_COMMIT();                                                          \
        } while (0)

    PROJ_STAGE_ISSUE(sb, 0);
    PROJ_STAGE_ISSUE(sb + PROJ_STAGE, 32);

    #pragma unroll 1
    for (int i = 0; i < 32; i++) {
        if (i == 31) CP_WAIT0(); else CP_WAIT1();
        __syncthreads();   // stage i visible; compute i-1 done on all threads

        if (i < 30) {
            const uint32_t bo = (uint32_t)(((i + 2) % 3) * PROJ_STAGE);
            PROJ_STAGE_ISSUE(sb + bo, (i + 2) * 32);
        }

        const uint32_t bb = sb + (uint32_t)((i % 3) * PROJ_STAGE);
        #pragma unroll
        for (int kc = 0; kc < 2; kc++) {
            uint32_t a[4][4];
            #pragma unroll
            for (int mt = 0; mt < 4; mt++)
                LDSM4(a[mt], bb + aoff + kc * 32 + mt * 1280);
            #pragma unroll
            for (int m = 0; m < 4; m++) {
                uint32_t bf[4];
                LDSM4(bf, bb + boff + kc * 32 + m * 1280);
                #pragma unroll
                for (int mt = 0; mt < 4; mt++) {
                    mma16(acc[mt][2 * m],     a[mt], bf[0], bf[1]);
                    mma16(acc[mt][2 * m + 1], a[mt], bf[2], bf[3]);
                }
            }
        }
    }

    #pragma unroll
    for (int mt = 0; mt < 4; mt++) {
        const int row = m0 + wm + mt * 16 + g;
        #pragma unroll
        for (int nt = 0; nt < 8; nt++) {
            const int col = n0 + wn + nt * 8 + c * 2;
            const float bv0 = bias[col], bv1 = bias[col + 1];
            *(__half2*)&out[(size_t)row * DMODEL + col] =
                __floats2half2_rn((acc[mt][nt][0] + bv0) * oscale,
                                  (acc[mt][nt][1] + bv1) * oscale);
            *(__half2*)&out[(size_t)(row + 8) * DMODEL + col] =
                __floats2half2_rn((acc[mt][nt][2] + bv0) * oscale,
                                  (acc[mt][nt][3] + bv1) * oscale);
        }
    }
    #undef PROJ_STAGE_ISSUE
}

// ---------------------------------------------------------------------------
// Kernel 2: flash attention, 256 q-rows/block (as R13) but Q fragments are
//   re-loaded per key tile via volatile LDSM (un-hoistable) -> 32 fewer
//   loop-resident registers, relieving the 255-reg cap seen in R13.
// Smem bytes: Qh 0 (36864) ; Kh 36864+buf*18432 ; Vh 73728+buf*18432 ;
//             Mh 110592..114688
// ---------------------------------------------------------------------------
#define QB 0
#define KB 36864
#define VB 73728
#define MB 110592
#define ATT_SMEM 114688

__global__ __launch_bounds__(256, 1)
void attn_h(float* __restrict__ out)
{
    extern __shared__ char smem[];
    const uint32_t sb = smem_u32(smem);
    __half* Mh = (__half*)(smem + MB);

    const int bh  = blockIdx.x;
    const int b   = bh >> 4;
    const int h   = bh & 15;
    const int q0  = blockIdx.y * 256;
    const int tid = threadIdx.x;
    const int lane = tid & 31;
    const int g   = lane >> 2;
    const int c   = lane & 3;
    const int mm  = lane >> 3;
    const int lr  = lane & 7;
    const int m0  = (tid >> 5) * 16;
    const size_t base = (size_t)b * DMODEL + h * HDIM;
    const __half* Qg = g_Q + base;
    const __half* Kg = g_K + base;
    const __half* Vg = g_V + base;

    const int nv = g_nv;
    const int ntiles = (nv + 127) >> 7;

    const int srow[4] = { (tid + 0)   >> 3, (tid + 256) >> 3,
                          (tid + 512) >> 3, (tid + 768) >> 3 };
    const int sseg = (tid & 7) * 8;

    // ---- prologue: Q (256 rows) + K0/V0 + mask + ones ----
    #pragma unroll
    for (int it = 0; it < 8; it++) {
        const int idx = tid + it * 256;
        const int r = idx >> 3;
        const int sg = (idx & 7) * 8;
        CP16(sb + QB + (uint32_t)(r * 144 + sg * 2),
             Qg + (size_t)(q0 + r) * RS + sg);
    }
    #pragma unroll
    for (int it = 0; it < 4; it++) {
        const int r = srow[it];
        const uint32_t d = (uint32_t)(r * 144 + sseg * 2);
        CP16(sb + KB + d, Kg + (size_t)r * RS + sseg);
        CP16(sb + VB + d, Vg + (size_t)r * RS + sseg);
    }
    CP_COMMIT();
    #pragma unroll
    for (int it = 0; it < 8; it++) {
        const int idx = tid + it * 256;
        Mh[idx] = (idx < nv) ? __float2half(1.0f) : __float2half(0.0f);
    }
    {
        const int buf = tid >> 7, r = tid & 127;
        const uint32_t ones = 0x3C003C00u;
        *(uint4*)(smem + VB + buf * 18432 + r * 144 + 128) =
            make_uint4(ones, ones, ones, ones);
    }
    CP_WAIT0();
    __syncthreads();

    const uint32_t qa = sb + QB +
        (uint32_t)(m0 + (mm & 1) * 8 + lr) * 144 + (mm >> 1) * 16;
    const uint32_t kfb = (uint32_t)(lr * 144 + mm * 16);
    const uint32_t vfb = (uint32_t)((mm * 8 + lr) * 144);

    float oA[8][4], oB[8][4];
    #pragma unroll
    for (int nt = 0; nt < 8; nt++)
        #pragma unroll
        for (int e = 0; e < 4; e++) { oA[nt][e] = 0.0f; oB[nt][e] = 0.0f; }
    float olA[4] = {0, 0, 0, 0}, olB[4] = {0, 0, 0, 0};

    #pragma unroll 1
    for (int t = 0; t < ntiles; t++) {
        if (t > 0) { CP_WAIT0(); __syncthreads(); }

        if (t + 1 < ntiles) {
            const int jn = (t + 1) * 128;
            const uint32_t bo = (uint32_t)(((t + 1) & 1) * 18432);
            #pragma unroll
            for (int it = 0; it < 4; it++) {
                const int r = srow[it];
                const uint32_t d = (uint32_t)(r * 144 + sseg * 2);
                CP16(sb + KB + bo + d, Kg + (size_t)(jn + r) * RS + sseg);
                CP16(sb + VB + bo + d, Vg + (size_t)(jn + r) * RS + sseg);
            }
            CP_COMMIT();
        }

        // Q fragments re-loaded per tile (volatile asm: cannot be hoisted,
        // keeps them out of the loop-carried register set)
        uint32_t qfA[4][4], qfB[4][4];
        #pragma unroll
        for (int kc = 0; kc < 4; kc++) {
            LDSM4(qfA[kc], qa + kc * 32);
            LDSM4(qfB[kc], qa + kc * 32 + 128 * 144);
        }

        const uint32_t kbuf = sb + KB + (uint32_t)((t & 1) * 18432);
        const uint32_t vbuf = sb + VB + (uint32_t)((t & 1) * 18432);
        const int j0 = t * 128;

        #pragma unroll
        for (int p = 0; p < 4; p++) {
            uint32_t pA[2][4], pB[2][4];
            #pragma unroll
            for (int q2 = 0; q2 < 2; q2++) {
                #pragma unroll
                for (int sub = 0; sub < 2; sub++) {
                    const int nt = p * 4 + q2 * 2 + sub;
                    float sA[4] = {0, 0, 0, 0}, sB[4] = {0, 0, 0, 0};
                    uint32_t kf0[4], kf1[4];
                    LDSM4(kf0, kbuf + kfb + nt * 1152);
                    LDSM4(kf1, kbuf + kfb + nt * 1152 + 64);
                    mma16(sA, qfA[0], kf0[0], kf0[1]);
                    mma16(sA, qfA[1], kf0[2], kf0[3]);
                    mma16(sA, qfA[2], kf1[0], kf1[1]);
                    mma16(sA, qfA[3], kf1[2], kf1[3]);
                    mma16(sB, qfB[0], kf0[0], kf0[1]);
                    mma16(sB, qfB[1], kf0[2], kf0[3]);
                    mma16(sB, qfB[2], kf1[0], kf1[1]);
                    mma16(sB, qfB[3], kf1[2], kf1[3]);

                    const uint32_t mk = *(const uint32_t*)&Mh[j0 + nt * 8 + 2 * c];
                    pA[q2][sub * 2]     = hmul2u(ex2h2(packh2(sA[0], sA[1])), mk);
                    pA[q2][sub * 2 + 1] = hmul2u(ex2h2(packh2(sA[2], sA[3])), mk);
                    pB[q2][sub * 2]     = hmul2u(ex2h2(packh2(sB[0], sB[1])), mk);
                    pB[q2][sub * 2 + 1] = hmul2u(ex2h2(packh2(sB[2], sB[3])), mk);
                }
            }
            #pragma unroll
            for (int ntd = 0; ntd < 8; ntd++) {
                uint32_t vf[4];
                LDSM4T(vf, vbuf + vfb + p * 4608 + ntd * 16);
                mma16(oA[ntd], pA[0], vf[0], vf[1]);
                mma16(oA[ntd], pA[1], vf[2], vf[3]);
                mma16(oB[ntd], pB[0], vf[0], vf[1]);
                mma16(oB[ntd], pB[1], vf[2], vf[3]);
            }
            {   // ones column: row sums on the tensor pipe (both subs)
                uint32_t vf1[4];
                LDSM4T(vf1, vbuf + vfb + p * 4608 + 8 * 16);
                mma16(olA, pA[0], vf1[0], vf1[1]);
                mma16(olA, pA[1], vf1[2], vf1[3]);
                mma16(olB, pB[0], vf1[0], vf1[1]);
                mma16(olB, pB[1], vf1[2], vf1[3]);
            }
        }
    }

    const float invA0 = 1.0f / olA[0], invA1 = 1.0f / olA[2];
    const float invB0 = 1.0f / olB[0], invB1 = 1.0f / olB[2];

    const int rA = q0 + m0 + g;
    const int rB = q0 + 128 + m0 + g;
    #pragma unroll
    for (int nt = 0; nt < 8; nt++) {
        const int d = nt * 8 + 2 * c;
        *(float2*)&out[(size_t)rA * RS + base + d] =
            make_float2(oA[nt][0] * invA0, oA[nt][1] * invA0);
        *(float2*)&out[(size_t)(rA + 8) * RS + base + d] =
            make_float2(oA[nt][2] * invA1, oA[nt][3] * invA1);
        *(float2*)&out[(size_t)rB * RS + base + d] =
            make_float2(oB[nt][0] * invB0, oB[nt][1] * invB0);
        *(float2*)&out[(size_t)(rB + 8) * RS + base + d] =
            make_float2(oB[nt][2] * invB1, oB[nt][3] * invB1);
    }
}

// ---------------------------------------------------------------------------
// Launcher. Inputs: query, key, value, mask, w_q, b_q, w_k, b_k, w_v, b_v.
// ---------------------------------------------------------------------------
extern "C" void kernel_launch(void* const* d_in, const int* in_sizes, int n_in,
                              void* d_out, int out_size)
{
    (void)in_sizes; (void)n_in; (void)out_size;
    const float* query = (const float*)d_in[0];
    const float* key_  = (const float*)d_in[1];
    const float* value = (const float*)d_in[2];
    const int*   mask  = (const int*)d_in[3];
    const float* w_q   = (const float*)d_in[4];
    const float* b_q   = (const float*)d_in[5];
    const float* w_k   = (const float*)d_in[6];
    const float* b_k   = (const float*)d_in[7];
    const float* w_v   = (const float*)d_in[8];
    const float* b_v   = (const float*)d_in[9];
    float* out = (float*)d_out;

    static bool attr_done = []() {
        cudaFuncSetAttribute(attn_h,
                             cudaFuncAttributeMaxDynamicSharedMemorySize,
                             ATT_SMEM);
        cudaFuncSetAttribute(qkv_proj_h,
                             cudaFuncAttributeMaxDynamicSharedMemorySize,
                             PROJ_SMEM);
        return true;
    }();
    (void)attr_done;

    scan_mask<<<1, 1024>>>(mask);

    dim3 gprep(S_LEN, 1, 6);
    prep<<<gprep, 256>>>(query, key_, value, w_q, w_k, w_v);

    dim3 gproj(DMODEL / 128, MROWS / 256, 3);   // (8, 16, 3)
    qkv_proj_h<<<gproj, 256, PROJ_SMEM>>>(b_q, b_k, b_v);

    dim3 gattn(BATCH * NHEAD, S_LEN / 256, 1);  // (32, 8)
    attn_h<<<gattn, 256, ATT_SMEM>>>(out);
}

// round 15
// speedup vs baseline: 1.0610x; 1.0610x over previous
#include <cuda_runtime.h>
#include <cuda_fp16.h>
#include <cstdint>

#define S_LEN  2048
#define BATCH  2
#define DMODEL 1024
#define NHEAD  16
#define HDIM   64
#define MROWS  (S_LEN * BATCH)   // 4096
#define RS     (BATCH * DMODEL)  // 2048

// Scratch (allocation-free: __device__ globals)
__device__ __half g_Q[(size_t)MROWS * DMODEL];
__device__ __half g_K[(size_t)MROWS * DMODEL];   // compacted keys
__device__ __half g_V[(size_t)MROWS * DMODEL];   // compacted values
__device__ __half g_Xh[3][(size_t)MROWS * DMODEL];   // xq full; xk/xv compacted
__device__ __half g_Wh[3][(size_t)DMODEL * DMODEL];
__device__ int    g_nv;
__device__ int    g_cidx[S_LEN];

// ---------------------------------------------------------------------------
// helpers
// ---------------------------------------------------------------------------
__device__ __forceinline__ uint32_t packh2(float a, float b) {
    __half2 h = __floats2half2_rn(a, b);
    return *(uint32_t*)&h;
}
__device__ __forceinline__ uint32_t smem_u32(const void* p) {
    uint32_t a;
    asm("{ .reg .u64 t; cvta.to.shared.u64 t, %1; cvt.u32.u64 %0, t; }"
        : "=r"(a) : "l"(p));
    return a;
}
__device__ __forceinline__ void mma16(float c[4], const uint32_t a[4],
                                      uint32_t b0, uint32_t b1) {
    asm volatile(
        "mma.sync.aligned.m16n8k16.row.col.f32.f16.f16.f32 "
        "{%0,%1,%2,%3}, {%4,%5,%6,%7}, {%8,%9}, {%0,%1,%2,%3};\n"
        : "+f"(c[0]), "+f"(c[1]), "+f"(c[2]), "+f"(c[3])
        : "r"(a[0]), "r"(a[1]), "r"(a[2]), "r"(a[3]), "r"(b0), "r"(b1));
}
__device__ __forceinline__ uint32_t ex2h2(uint32_t s) {
    uint32_t r;
    asm("ex2.approx.f16x2 %0, %1;" : "=r"(r) : "r"(s));
    return r;
}
__device__ __forceinline__ uint32_t hmul2u(uint32_t a, uint32_t b) {
    uint32_t r;
    asm("mul.rn.f16x2 %0, %1, %2;" : "=r"(r) : "r"(a), "r"(b));
    return r;
}
#define LDSM4(r, addr) \
    asm volatile("ldmatrix.sync.aligned.m8n8.x4.shared.b16 {%0,%1,%2,%3}, [%4];" \
        : "=r"((r)[0]), "=r"((r)[1]), "=r"((r)[2]), "=r"((r)[3]) : "r"(addr))
#define LDSM4T(r, addr) \
    asm volatile("ldmatrix.sync.aligned.m8n8.x4.trans.shared.b16 {%0,%1,%2,%3}, [%4];" \
        : "=r"((r)[0]), "=r"((r)[1]), "=r"((r)[2]), "=r"((r)[3]) : "r"(addr))
#define CP16(dst, src) \
    asm volatile("cp.async.cg.shared.global [%0], [%1], 16;" :: "r"(dst), "l"(src))
#define CP_COMMIT() asm volatile("cp.async.commit_group;" ::: "memory")
#define CP_WAIT0()  asm volatile("cp.async.wait_group 0;" ::: "memory")
#define CP_WAIT1()  asm volatile("cp.async.wait_group 1;" ::: "memory")

// ---------------------------------------------------------------------------
// Kernel A: mask prefix-scan -> g_cidx, g_nv.  (R13, unchanged)
// ---------------------------------------------------------------------------
__global__ __launch_bounds__(1024)
void scan_mask(const int* __restrict__ mask)
{
    __shared__ int wsum[32];
    const int tid  = threadIdx.x;
    const int lane = tid & 31;
    const int w    = tid >> 5;
    const int e0 = (mask[2 * tid] != 0);
    const int e1 = (mask[2 * tid + 1] != 0);
    const int cnt = e0 + e1;

    int x = cnt;
    #pragma unroll
    for (int o = 1; o < 32; o <<= 1) {
        int y = __shfl_up_sync(0xffffffffu, x, o);
        if (lane >= o) x += y;
    }
    if (lane == 31) wsum[w] = x;
    __syncthreads();
    if (w == 0) {
        int s = wsum[lane];
        #pragma unroll
        for (int o = 1; o < 32; o <<= 1) {
            int y = __shfl_up_sync(0xffffffffu, s, o);
            if (lane >= o) s += y;
        }
        wsum[lane] = s;
    }
    __syncthreads();
    const int incl = x + (w > 0 ? wsum[w - 1] : 0);
    const int excl = incl - cnt;
    if (e0) g_cidx[excl] = 2 * tid;
    if (e1) g_cidx[excl + e0] = 2 * tid + 1;
    if (tid == 1023) g_nv = incl;
}

// ---------------------------------------------------------------------------
// Kernel B: prep (R13, unchanged).
// ---------------------------------------------------------------------------
__global__ __launch_bounds__(256)
void prep(const float* __restrict__ xq, const float* __restrict__ xk,
          const float* __restrict__ xv, const float* __restrict__ w0,
          const float* __restrict__ w1, const float* __restrict__ w2)
{
    const int z = blockIdx.z;
    if (z >= 4) {
        const int p  = blockIdx.x;
        const int nv = g_nv;
        const int nvp = (nv + 127) & ~127;
        if (p >= nvp) return;
        __half* dst = (z == 4 ? g_Xh[1] : g_Xh[2]) + (size_t)p * RS;
        const int i = threadIdx.x * 8;
        if (p < nv) {
            const int s = g_cidx[p];
            const float* src = (z == 4 ? xk : xv) + (size_t)s * RS;
            float4 a = *(const float4*)&src[i];
            float4 b = *(const float4*)&src[i + 4];
            __half2 h0 = __floats2half2_rn(a.x, a.y);
            __half2 h1 = __floats2half2_rn(a.z, a.w);
            __half2 h2 = __floats2half2_rn(b.x, b.y);
            __half2 h3 = __floats2half2_rn(b.z, b.w);
            *(uint4*)&dst[i] = make_uint4(*(uint32_t*)&h0, *(uint32_t*)&h1,
                                          *(uint32_t*)&h2, *(uint32_t*)&h3);
        } else {
            *(uint4*)&dst[i] = make_uint4(0, 0, 0, 0);
        }
        return;
    }
    const float* s; __half* d; size_t n;
    switch (z) {
        case 0: s = xq; d = g_Xh[0]; n = (size_t)MROWS * DMODEL; break;
        case 1: s = w0; d = g_Wh[0]; n = (size_t)DMODEL * DMODEL; break;
        case 2: s = w1; d = g_Wh[1]; n = (size_t)DMODEL * DMODEL; break;
        default: s = w2; d = g_Wh[2]; n = (size_t)DMODEL * DMODEL; break;
    }
    const size_t n4 = n >> 2;
    const size_t stride = (size_t)gridDim.x * blockDim.x;
    for (size_t i = (size_t)blockIdx.x * blockDim.x + threadIdx.x; i < n4;
         i += stride) {
        float4 v = *(const float4*)&s[i * 4];
        __half2 h0 = __floats2half2_rn(v.x, v.y);
        __half2 h1 = __floats2half2_rn(v.z, v.w);
        *(uint2*)&d[i * 4] = make_uint2(*(uint32_t*)&h0, *(uint32_t*)&h1);
    }
}

// ---------------------------------------------------------------------------
// Kernel 1: QKV projection (exact R13 version: 128x128 tile, 2 CTAs/SM).
// ---------------------------------------------------------------------------
__global__ __launch_bounds__(256, 2)
void qkv_proj_h(const float* __restrict__ Bq, const float* __restrict__ Bk,
                const float* __restrict__ Bv)
{
    const int m0 = blockIdx.y * 128;
    if (blockIdx.z != 0) {
        const int nvp = (g_nv + 127) & ~127;
        if (m0 >= 2 * nvp) return;
    }
    const __half* X = g_Xh[blockIdx.z];
    const __half* W = g_Wh[blockIdx.z];
    const float* bias; __half* out; float oscale;
    if (blockIdx.z == 0)      { bias = Bq; out = g_Q; oscale = 0.125f * 1.44269504f; }
    else if (blockIdx.z == 1) { bias = Bk; out = g_K; oscale = 1.0f; }
    else                      { bias = Bv; out = g_V; oscale = 1.0f; }

    __shared__ __align__(16) char smem[3 * 20480];
    const uint32_t sb = smem_u32(smem);

    const int tid  = threadIdx.x;
    const int wid  = tid >> 5;
    const int lane = tid & 31;
    const int g    = lane >> 2;
    const int c    = lane & 3;
    const int mm   = lane >> 3;
    const int lr   = lane & 7;
    const int wm   = (wid & 3) * 32;
    const int wn   = (wid >> 2) * 64;
    const int n0   = blockIdx.x * 128;

    const int c0r = tid >> 2,         c0c = (tid & 3);
    const int c1r = (tid + 256) >> 2, c1c = (tid & 3);
    const __half* Xs0 = X + (size_t)(m0 + c0r) * DMODEL + c0c * 8;
    const __half* Xs1 = X + (size_t)(m0 + c1r) * DMODEL + c1c * 8;
    const __half* Ws0 = W + (size_t)(n0 + c0r) * DMODEL + c0c * 8;
    const __half* Ws1 = W + (size_t)(n0 + c1r) * DMODEL + c1c * 8;
    const uint32_t d0 = (uint32_t)(c0r * 80 + c0c * 16);
    const uint32_t d1 = (uint32_t)(c1r * 80 + c1c * 16);

    const uint32_t aoff = (uint32_t)((wm + (mm & 1) * 8 + lr) * 80 + (mm >> 1) * 16);
    const uint32_t boff = (uint32_t)(10240 + (wn + (mm >> 1) * 8 + lr) * 80 + (mm & 1) * 16);

    float acc[2][8][4];
    #pragma unroll
    for (int mt = 0; mt < 2; mt++)
        #pragma unroll
        for (int nt = 0; nt < 8; nt++)
            #pragma unroll
            for (int e = 0; e < 4; e++) acc[mt][nt][e] = 0.0f;

    CP16(sb + d0, Xs0); CP16(sb + d1, Xs1);
    CP16(sb + 10240 + d0, Ws0); CP16(sb + 10240 + d1, Ws1);
    CP_COMMIT();
    CP16(sb + 20480 + d0, Xs0 + 32); CP16(sb + 20480 + d1, Xs1 + 32);
    CP16(sb + 30720 + d0, Ws0 + 32); CP16(sb + 30720 + d1, Ws1 + 32);
    CP_COMMIT();

    #pragma unroll 1
    for (int i = 0; i < 32; i++) {
        if (i == 31) CP_WAIT0(); else CP_WAIT1();
        __syncthreads();

        if (i < 30) {
            const int kn = (i + 2) * 32;
            const uint32_t bo = (uint32_t)(((i + 2) % 3) * 20480);
            CP16(sb + bo + d0, Xs0 + kn); CP16(sb + bo + d1, Xs1 + kn);
            CP16(sb + bo + 10240 + d0, Ws0 + kn); CP16(sb + bo + 10240 + d1, Ws1 + kn);
            CP_COMMIT();
        }

        const uint32_t bb = sb + (uint32_t)((i % 3) * 20480);
        #pragma unroll
        for (int kc = 0; kc < 2; kc++) {
            uint32_t a0[4], a1[4];
            LDSM4(a0, bb + aoff + kc * 32);
            LDSM4(a1, bb + aoff + kc * 32 + 1280);
            #pragma unroll
            for (int m = 0; m < 4; m++) {
                uint32_t bf[4];
                LDSM4(bf, bb + boff + kc * 32 + m * 1280);
                mma16(acc[0][2 * m],     a0, bf[0], bf[1]);
                mma16(acc[0][2 * m + 1], a0, bf[2], bf[3]);
                mma16(acc[1][2 * m],     a1, bf[0], bf[1]);
                mma16(acc[1][2 * m + 1], a1, bf[2], bf[3]);
            }
        }
    }

    #pragma unroll
    for (int mt = 0; mt < 2; mt++) {
        const int row = m0 + wm + mt * 16 + g;
        #pragma unroll
        for (int nt = 0; nt < 8; nt++) {
            const int col = n0 + wn + nt * 8 + c * 2;
            const float bv0 = bias[col], bv1 = bias[col + 1];
            *(__half2*)&out[(size_t)row * DMODEL + col] =
                __floats2half2_rn((acc[mt][nt][0] + bv0) * oscale,
                                  (acc[mt][nt][1] + bv1) * oscale);
            *(__half2*)&out[(size_t)(row + 8) * DMODEL + col] =
                __floats2half2_rn((acc[mt][nt][2] + bv0) * oscale,
                                  (acc[mt][nt][3] + bv1) * oscale);
        }
    }
}

// ---------------------------------------------------------------------------
// Kernel 2: flash attention (R13 structure: 256 q-rows/block, hoisted Q
//   fragments) with ONE change: QK accumulation split into two depth-2
//   chains merged by FADD -> 2x the independent HMMA chains in flight.
// Smem bytes: Qh 0 (36864) ; Kh 36864+buf*18432 ; Vh 73728+buf*18432 ;
//             Mh 110592..114688
// ---------------------------------------------------------------------------
#define QB 0
#define KB 36864
#define VB 73728
#define MB 110592
#define ATT_SMEM 114688

__global__ __launch_bounds__(256, 1)
void attn_h(float* __restrict__ out)
{
    extern __shared__ char smem[];
    const uint32_t sb = smem_u32(smem);
    __half* Mh = (__half*)(smem + MB);

    const int bh  = blockIdx.x;
    const int b   = bh >> 4;
    const int h   = bh & 15;
    const int q0  = blockIdx.y * 256;
    const int tid = threadIdx.x;
    const int lane = tid & 31;
    const int g   = lane >> 2;
    const int c   = lane & 3;
    const int mm  = lane >> 3;
    const int lr  = lane & 7;
    const int m0  = (tid >> 5) * 16;
    const size_t base = (size_t)b * DMODEL + h * HDIM;
    const __half* Qg = g_Q + base;
    const __half* Kg = g_K + base;
    const __half* Vg = g_V + base;

    const int nv = g_nv;
    const int ntiles = (nv + 127) >> 7;

    const int srow[4] = { (tid + 0)   >> 3, (tid + 256) >> 3,
                          (tid + 512) >> 3, (tid + 768) >> 3 };
    const int sseg = (tid & 7) * 8;

    // ---- prologue: Q (256 rows) + K0/V0 + mask + ones ----
    #pragma unroll
    for (int it = 0; it < 8; it++) {
        const int idx = tid + it * 256;
        const int r = idx >> 3;
        const int sg = (idx & 7) * 8;
        CP16(sb + QB + (uint32_t)(r * 144 + sg * 2),
             Qg + (size_t)(q0 + r) * RS + sg);
    }
    #pragma unroll
    for (int it = 0; it < 4; it++) {
        const int r = srow[it];
        const uint32_t d = (uint32_t)(r * 144 + sseg * 2);
        CP16(sb + KB + d, Kg + (size_t)r * RS + sseg);
        CP16(sb + VB + d, Vg + (size_t)r * RS + sseg);
    }
    CP_COMMIT();
    #pragma unroll
    for (int it = 0; it < 8; it++) {
        const int idx = tid + it * 256;
        Mh[idx] = (idx < nv) ? __float2half(1.0f) : __float2half(0.0f);
    }
    {
        const int buf = tid >> 7, r = tid & 127;
        const uint32_t ones = 0x3C003C00u;
        *(uint4*)(smem + VB + buf * 18432 + r * 144 + 128) =
            make_uint4(ones, ones, ones, ones);
    }
    CP_WAIT0();
    __syncthreads();

    // ---- hoist Q fragments for both sub-blocks (R13 style) ----
    uint32_t qfA[4][4], qfB[4][4];
    {
        const uint32_t qa = sb + QB +
            (uint32_t)(m0 + (mm & 1) * 8 + lr) * 144 + (mm >> 1) * 16;
        #pragma unroll
        for (int kc = 0; kc < 4; kc++) {
            LDSM4(qfA[kc], qa + kc * 32);
            LDSM4(qfB[kc], qa + kc * 32 + 128 * 144);
        }
    }

    const uint32_t kfb = (uint32_t)(lr * 144 + mm * 16);
    const uint32_t vfb = (uint32_t)((mm * 8 + lr) * 144);

    float oA[8][4], oB[8][4];
    #pragma unroll
    for (int nt = 0; nt < 8; nt++)
        #pragma unroll
        for (int e = 0; e < 4; e++) { oA[nt][e] = 0.0f; oB[nt][e] = 0.0f; }
    float olA[4] = {0, 0, 0, 0}, olB[4] = {0, 0, 0, 0};

    #pragma unroll 1
    for (int t = 0; t < ntiles; t++) {
        if (t > 0) { CP_WAIT0(); __syncthreads(); }

        if (t + 1 < ntiles) {
            const int jn = (t + 1) * 128;
            const uint32_t bo = (uint32_t)(((t + 1) & 1) * 18432);
            #pragma unroll
            for (int it = 0; it < 4; it++) {
                const int r = srow[it];
                const uint32_t d = (uint32_t)(r * 144 + sseg * 2);
                CP16(sb + KB + bo + d, Kg + (size_t)(jn + r) * RS + sseg);
                CP16(sb + VB + bo + d, Vg + (size_t)(jn + r) * RS + sseg);
            }
            CP_COMMIT();
        }

        const uint32_t kbuf = sb + KB + (uint32_t)((t & 1) * 18432);
        const uint32_t vbuf = sb + VB + (uint32_t)((t & 1) * 18432);
        const int j0 = t * 128;

        #pragma unroll
        for (int p = 0; p < 4; p++) {
            uint32_t pA[2][4], pB[2][4];
            #pragma unroll
            for (int q2 = 0; q2 < 2; q2++) {
                #pragma unroll
                for (int sub = 0; sub < 2; sub++) {
                    const int nt = p * 4 + q2 * 2 + sub;
                    // split QK chains: two depth-2 chains per sub-block
                    float sA0[4] = {0, 0, 0, 0}, sA1[4] = {0, 0, 0, 0};
                    float sB0[4] = {0, 0, 0, 0}, sB1[4] = {0, 0, 0, 0};
                    uint32_t kf0[4], kf1[4];
                    LDSM4(kf0, kbuf + kfb + nt * 1152);
                    LDSM4(kf1, kbuf + kfb + nt * 1152 + 64);
                    mma16(sA0, qfA[0], kf0[0], kf0[1]);
                    mma16(sA1, qfA[2], kf1[0], kf1[1]);
                    mma16(sB0, qfB[0], kf0[0], kf0[1]);
                    mma16(sB1, qfB[2], kf1[0], kf1[1]);
                    mma16(sA0, qfA[1], kf0[2], kf0[3]);
                    mma16(sA1, qfA[3], kf1[2], kf1[3]);
                    mma16(sB0, qfB[1], kf0[2], kf0[3]);
                    mma16(sB1, qfB[3], kf1[2], kf1[3]);

                    const uint32_t mk = *(const uint32_t*)&Mh[j0 + nt * 8 + 2 * c];
                    pA[q2][sub * 2] = hmul2u(
                        ex2h2(packh2(sA0[0] + sA1[0], sA0[1] + sA1[1])), mk);
                    pA[q2][sub * 2 + 1] = hmul2u(
                        ex2h2(packh2(sA0[2] + sA1[2], sA0[3] + sA1[3])), mk);
                    pB[q2][sub * 2] = hmul2u(
                        ex2h2(packh2(sB0[0] + sB1[0], sB0[1] + sB1[1])), mk);
                    pB[q2][sub * 2 + 1] = hmul2u(
                        ex2h2(packh2(sB0[2] + sB1[2], sB0[3] + sB1[3])), mk);
                }
            }
            #pragma unroll
            for (int ntd = 0; ntd < 8; ntd++) {
                uint32_t vf[4];
                LDSM4T(vf, vbuf + vfb + p * 4608 + ntd * 16);
                mma16(oA[ntd], pA[0], vf[0], vf[1]);
                mma16(oA[ntd], pA[1], vf[2], vf[3]);
                mma16(oB[ntd], pB[0], vf[0], vf[1]);
                mma16(oB[ntd], pB[1], vf[2], vf[3]);
            }
            {   // ones column: row sums on the tensor pipe (both subs)
                uint32_t vf1[4];
                LDSM4T(vf1, vbuf + vfb + p * 4608 + 8 * 16);
                mma16(olA, pA[0], vf1[0], vf1[1]);
                mma16(olA, pA[1], vf1[2], vf1[3]);
                mma16(olB, pB[0], vf1[0], vf1[1]);
                mma16(olB, pB[1], vf1[2], vf1[3]);
            }
        }
    }

    const float invA0 = 1.0f / olA[0], invA1 = 1.0f / olA[2];
    const float invB0 = 1.0f / olB[0], invB1 = 1.0f / olB[2];

    const int rA = q0 + m0 + g;
    const int rB = q0 + 128 + m0 + g;
    #pragma unroll
    for (int nt = 0; nt < 8; nt++) {
        const int d = nt * 8 + 2 * c;
        *(float2*)&out[(size_t)rA * RS + base + d] =
            make_float2(oA[nt][0] * invA0, oA[nt][1] * invA0);
        *(float2*)&out[(size_t)(rA + 8) * RS + base + d] =
            make_float2(oA[nt][2] * invA1, oA[nt][3] * invA1);
        *(float2*)&out[(size_t)rB * RS + base + d] =
            make_float2(oB[nt][0] * invB0, oB[nt][1] * invB0);
        *(float2*)&out[(size_t)(rB + 8) * RS + base + d] =
            make_float2(oB[nt][2] * invB1, oB[nt][3] * invB1);
    }
}

// ---------------------------------------------------------------------------
// Launcher. Inputs: query, key, value, mask, w_q, b_q, w_k, b_k, w_v, b_v.
// ---------------------------------------------------------------------------
extern "C" void kernel_launch(void* const* d_in, const int* in_sizes, int n_in,
                              void* d_out, int out_size)
{
    (void)in_sizes; (void)n_in; (void)out_size;
    const float* query = (const float*)d_in[0];
    const float* key_  = (const float*)d_in[1];
    const float* value = (const float*)d_in[2];
    const int*   mask  = (const int*)d_in[3];
    const float* w_q   = (const float*)d_in[4];
    const float* b_q   = (const float*)d_in[5];
    const float* w_k   = (const float*)d_in[6];
    const float* b_k   = (const float*)d_in[7];
    const float* w_v   = (const float*)d_in[8];
    const float* b_v   = (const float*)d_in[9];
    float* out = (float*)d_out;

    static bool attr_done = []() {
        cudaFuncSetAttribute(attn_h,
                             cudaFuncAttributeMaxDynamicSharedMemorySize,
                             ATT_SMEM);
        return true;
    }();
    (void)attr_done;

    scan_mask<<<1, 1024>>>(mask);

    dim3 gprep(S_LEN, 1, 6);
    prep<<<gprep, 256>>>(query, key_, value, w_q, w_k, w_v);

    dim3 gproj(DMODEL / 128, MROWS / 128, 3);   // (8, 32, 3)
    qkv_proj_h<<<gproj, 256>>>(b_q, b_k, b_v);

    dim3 gattn(BATCH * NHEAD, S_LEN / 256, 1);  // (32, 8)
    attn_h<<<gattn, 256, ATT_SMEM>>>(out);
}

// round 16
// speedup vs baseline: 1.1177x; 1.0534x over previous
#include <cuda_runtime.h>
#include <cuda_fp16.h>
#include <cstdint>

#define S_LEN  2048
#define BATCH  2
#define DMODEL 1024
#define NHEAD  16
#define HDIM   64
#define MROWS  (S_LEN * BATCH)   // 4096
#define RS     (BATCH * DMODEL)  // 2048

// Scratch (allocation-free: __device__ globals)
__device__ __half g_Q[(size_t)MROWS * DMODEL];
__device__ __half g_K[(size_t)MROWS * DMODEL];   // compacted keys
__device__ __half g_V[(size_t)MROWS * DMODEL];   // compacted values
__device__ __half g_Xh[3][(size_t)MROWS * DMODEL];   // xq full; xk/xv compacted
__device__ __half g_Wh[3][(size_t)DMODEL * DMODEL];
__device__ int    g_nv;
__device__ int    g_cidx[S_LEN];

// ---------------------------------------------------------------------------
// helpers
// ---------------------------------------------------------------------------
__device__ __forceinline__ uint32_t packh2(float a, float b) {
    __half2 h = __floats2half2_rn(a, b);
    return *(uint32_t*)&h;
}
__device__ __forceinline__ uint32_t smem_u32(const void* p) {
    uint32_t a;
    asm("{ .reg .u64 t; cvta.to.shared.u64 t, %1; cvt.u32.u64 %0, t; }"
        : "=r"(a) : "l"(p));
    return a;
}
__device__ __forceinline__ void mma16(float c[4], const uint32_t a[4],
                                      uint32_t b0, uint32_t b1) {
    asm volatile(
        "mma.sync.aligned.m16n8k16.row.col.f32.f16.f16.f32 "
        "{%0,%1,%2,%3}, {%4,%5,%6,%7}, {%8,%9}, {%0,%1,%2,%3};\n"
        : "+f"(c[0]), "+f"(c[1]), "+f"(c[2]), "+f"(c[3])
        : "r"(a[0]), "r"(a[1]), "r"(a[2]), "r"(a[3]), "r"(b0), "r"(b1));
}
__device__ __forceinline__ uint32_t ex2h2(uint32_t s) {
    uint32_t r;
    asm("ex2.approx.f16x2 %0, %1;" : "=r"(r) : "r"(s));
    return r;
}
__device__ __forceinline__ uint32_t hmul2u(uint32_t a, uint32_t b) {
    uint32_t r;
    asm("mul.rn.f16x2 %0, %1, %2;" : "=r"(r) : "r"(a), "r"(b));
    return r;
}
#define LDSM4(r, addr) \
    asm volatile("ldmatrix.sync.aligned.m8n8.x4.shared.b16 {%0,%1,%2,%3}, [%4];" \
        : "=r"((r)[0]), "=r"((r)[1]), "=r"((r)[2]), "=r"((r)[3]) : "r"(addr))
#define LDSM4T(r, addr) \
    asm volatile("ldmatrix.sync.aligned.m8n8.x4.trans.shared.b16 {%0,%1,%2,%3}, [%4];" \
        : "=r"((r)[0]), "=r"((r)[1]), "=r"((r)[2]), "=r"((r)[3]) : "r"(addr))
#define CP16(dst, src) \
    asm volatile("cp.async.cg.shared.global [%0], [%1], 16;" :: "r"(dst), "l"(src))
#define CP_COMMIT() asm volatile("cp.async.commit_group;" ::: "memory")
#define CP_WAIT0()  asm volatile("cp.async.wait_group 0;" ::: "memory")
#define CP_WAIT1()  asm volatile("cp.async.wait_group 1;" ::: "memory")

// ---------------------------------------------------------------------------
// Kernel A: mask prefix-scan -> g_cidx, g_nv.  (R13, unchanged)
// ---------------------------------------------------------------------------
__global__ __launch_bounds__(1024)
void scan_mask(const int* __restrict__ mask)
{
    __shared__ int wsum[32];
    const int tid  = threadIdx.x;
    const int lane = tid & 31;
    const int w    = tid >> 5;
    const int e0 = (mask[2 * tid] != 0);
    const int e1 = (mask[2 * tid + 1] != 0);
    const int cnt = e0 + e1;

    int x = cnt;
    #pragma unroll
    for (int o = 1; o < 32; o <<= 1) {
        int y = __shfl_up_sync(0xffffffffu, x, o);
        if (lane >= o) x += y;
    }
    if (lane == 31) wsum[w] = x;
    __syncthreads();
    if (w == 0) {
        int s = wsum[lane];
        #pragma unroll
        for (int o = 1; o < 32; o <<= 1) {
            int y = __shfl_up_sync(0xffffffffu, s, o);
            if (lane >= o) s += y;
        }
        wsum[lane] = s;
    }
    __syncthreads();
    const int incl = x + (w > 0 ? wsum[w - 1] : 0);
    const int excl = incl - cnt;
    if (e0) g_cidx[excl] = 2 * tid;
    if (e1) g_cidx[excl + e0] = 2 * tid + 1;
    if (tid == 1023) g_nv = incl;
}

// ---------------------------------------------------------------------------
// Kernel B: prep (R13, unchanged).
// ---------------------------------------------------------------------------
__global__ __launch_bounds__(256)
void prep(const float* __restrict__ xq, const float* __restrict__ xk,
          const float* __restrict__ xv, const float* __restrict__ w0,
          const float* __restrict__ w1, const float* __restrict__ w2)
{
    const int z = blockIdx.z;
    if (z >= 4) {
        const int p  = blockIdx.x;
        const int nv = g_nv;
        const int nvp = (nv + 127) & ~127;
        if (p >= nvp) return;
        __half* dst = (z == 4 ? g_Xh[1] : g_Xh[2]) + (size_t)p * RS;
        const int i = threadIdx.x * 8;
        if (p < nv) {
            const int s = g_cidx[p];
            const float* src = (z == 4 ? xk : xv) + (size_t)s * RS;
            float4 a = *(const float4*)&src[i];
            float4 b = *(const float4*)&src[i + 4];
            __half2 h0 = __floats2half2_rn(a.x, a.y);
            __half2 h1 = __floats2half2_rn(a.z, a.w);
            __half2 h2 = __floats2half2_rn(b.x, b.y);
            __half2 h3 = __floats2half2_rn(b.z, b.w);
            *(uint4*)&dst[i] = make_uint4(*(uint32_t*)&h0, *(uint32_t*)&h1,
                                          *(uint32_t*)&h2, *(uint32_t*)&h3);
        } else {
            *(uint4*)&dst[i] = make_uint4(0, 0, 0, 0);
        }
        return;
    }
    const float* s; __half* d; size_t n;
    switch (z) {
        case 0: s = xq; d = g_Xh[0]; n = (size_t)MROWS * DMODEL; break;
        case 1: s = w0; d = g_Wh[0]; n = (size_t)DMODEL * DMODEL; break;
        case 2: s = w1; d = g_Wh[1]; n = (size_t)DMODEL * DMODEL; break;
        default: s = w2; d = g_Wh[2]; n = (size_t)DMODEL * DMODEL; break;
    }
    const size_t n4 = n >> 2;
    const size_t stride = (size_t)gridDim.x * blockDim.x;
    for (size_t i = (size_t)blockIdx.x * blockDim.x + threadIdx.x; i < n4;
         i += stride) {
        float4 v = *(const float4*)&s[i * 4];
        __half2 h0 = __floats2half2_rn(v.x, v.y);
        __half2 h1 = __floats2half2_rn(v.z, v.w);
        *(uint2*)&d[i * 4] = make_uint2(*(uint32_t*)&h0, *(uint32_t*)&h1);
    }
}

// ---------------------------------------------------------------------------
// Kernel 1: QKV projection (exact R13 version: 128x128 tile, 2 CTAs/SM).
// ---------------------------------------------------------------------------
__global__ __launch_bounds__(256, 2)
void qkv_proj_h(const float* __restrict__ Bq, const float* __restrict__ Bk,
                const float* __restrict__ Bv)
{
    const int m0 = blockIdx.y * 128;
    if (blockIdx.z != 0) {
        const int nvp = (g_nv + 127) & ~127;
        if (m0 >= 2 * nvp) return;
    }
    const __half* X = g_Xh[blockIdx.z];
    const __half* W = g_Wh[blockIdx.z];
    const float* bias; __half* out; float oscale;
    if (blockIdx.z == 0)      { bias = Bq; out = g_Q; oscale = 0.125f * 1.44269504f; }
    else if (blockIdx.z == 1) { bias = Bk; out = g_K; oscale = 1.0f; }
    else                      { bias = Bv; out = g_V; oscale = 1.0f; }

    __shared__ __align__(16) char smem[3 * 20480];
    const uint32_t sb = smem_u32(smem);

    const int tid  = threadIdx.x;
    const int wid  = tid >> 5;
    const int lane = tid & 31;
    const int g    = lane >> 2;
    const int c    = lane & 3;
    const int mm   = lane >> 3;
    const int lr   = lane & 7;
    const int wm   = (wid & 3) * 32;
    const int wn   = (wid >> 2) * 64;
    const int n0   = blockIdx.x * 128;

    const int c0r = tid >> 2,         c0c = (tid & 3);
    const int c1r = (tid + 256) >> 2, c1c = (tid & 3);
    const __half* Xs0 = X + (size_t)(m0 + c0r) * DMODEL + c0c * 8;
    const __half* Xs1 = X + (size_t)(m0 + c1r) * DMODEL + c1c * 8;
    const __half* Ws0 = W + (size_t)(n0 + c0r) * DMODEL + c0c * 8;
    const __half* Ws1 = W + (size_t)(n0 + c1r) * DMODEL + c1c * 8;
    const uint32_t d0 = (uint32_t)(c0r * 80 + c0c * 16);
    const uint32_t d1 = (uint32_t)(c1r * 80 + c1c * 16);

    const uint32_t aoff = (uint32_t)((wm + (mm & 1) * 8 + lr) * 80 + (mm >> 1) * 16);
    const uint32_t boff = (uint32_t)(10240 + (wn + (mm >> 1) * 8 + lr) * 80 + (mm & 1) * 16);

    float acc[2][8][4];
    #pragma unroll
    for (int mt = 0; mt < 2; mt++)
        #pragma unroll
        for (int nt = 0; nt < 8; nt++)
            #pragma unroll
            for (int e = 0; e < 4; e++) acc[mt][nt][e] = 0.0f;

    CP16(sb + d0, Xs0); CP16(sb + d1, Xs1);
    CP16(sb + 10240 + d0, Ws0); CP16(sb + 10240 + d1, Ws1);
    CP_COMMIT();
    CP16(sb + 20480 + d0, Xs0 + 32); CP16(sb + 20480 + d1, Xs1 + 32);
    CP16(sb + 30720 + d0, Ws0 + 32); CP16(sb + 30720 + d1, Ws1 + 32);
    CP_COMMIT();

    #pragma unroll 1
    for (int i = 0; i < 32; i++) {
        if (i == 31) CP_WAIT0(); else CP_WAIT1();
        __syncthreads();

        if (i < 30) {
            const int kn = (i + 2) * 32;
            const uint32_t bo = (uint32_t)(((i + 2) % 3) * 20480);
            CP16(sb + bo + d0, Xs0 + kn); CP16(sb + bo + d1, Xs1 + kn);
            CP16(sb + bo + 10240 + d0, Ws0 + kn); CP16(sb + bo + 10240 + d1, Ws1 + kn);
            CP_COMMIT();
        }

        const uint32_t bb = sb + (uint32_t)((i % 3) * 20480);
        #pragma unroll
        for (int kc = 0; kc < 2; kc++) {
            uint32_t a0[4], a1[4];
            LDSM4(a0, bb + aoff + kc * 32);
            LDSM4(a1, bb + aoff + kc * 32 + 1280);
            #pragma unroll
            for (int m = 0; m < 4; m++) {
                uint32_t bf[4];
                LDSM4(bf, bb + boff + kc * 32 + m * 1280);
                mma16(acc[0][2 * m],     a0, bf[0], bf[1]);
                mma16(acc[0][2 * m + 1], a0, bf[2], bf[3]);
                mma16(acc[1][2 * m],     a1, bf[0], bf[1]);
                mma16(acc[1][2 * m + 1], a1, bf[2], bf[3]);
            }
        }
    }

    #pragma unroll
    for (int mt = 0; mt < 2; mt++) {
        const int row = m0 + wm + mt * 16 + g;
        #pragma unroll
        for (int nt = 0; nt < 8; nt++) {
            const int col = n0 + wn + nt * 8 + c * 2;
            const float bv0 = bias[col], bv1 = bias[col + 1];
            *(__half2*)&out[(size_t)row * DMODEL + col] =
                __floats2half2_rn((acc[mt][nt][0] + bv0) * oscale,
                                  (acc[mt][nt][1] + bv1) * oscale);
            *(__half2*)&out[(size_t)(row + 8) * DMODEL + col] =
                __floats2half2_rn((acc[mt][nt][2] + bv0) * oscale,
                                  (acc[mt][nt][3] + bv1) * oscale);
        }
    }
}

// ---------------------------------------------------------------------------
// Kernel 2: flash attention (R13 mainloop) with work removal only:
//   - ones-column B fragment is the constant 0x3C003C00 (no LDSM, no V-pad
//     smem fill),
//   - mask multiply + Mh load only on the LAST key tile (all compacted keys
//     in earlier tiles are valid; pad keys exist only in the tail).
// Smem bytes: Qh 0 (36864) ; Kh 36864+buf*18432 ; Vh 73728+buf*18432 ;
//             Mh 110592..114688
// ---------------------------------------------------------------------------
#define QB 0
#define KB 36864
#define VB 73728
#define MB 110592
#define ATT_SMEM 114688
#define ONEH2 0x3C003C00u

__global__ __launch_bounds__(256, 1)
void attn_h(float* __restrict__ out)
{
    extern __shared__ char smem[];
    const uint32_t sb = smem_u32(smem);
    __half* Mh = (__half*)(smem + MB);

    const int bh  = blockIdx.x;
    const int b   = bh >> 4;
    const int h   = bh & 15;
    const int q0  = blockIdx.y * 256;
    const int tid = threadIdx.x;
    const int lane = tid & 31;
    const int g   = lane >> 2;
    const int c   = lane & 3;
    const int mm  = lane >> 3;
    const int lr  = lane & 7;
    const int m0  = (tid >> 5) * 16;
    const size_t base = (size_t)b * DMODEL + h * HDIM;
    const __half* Qg = g_Q + base;
    const __half* Kg = g_K + base;
    const __half* Vg = g_V + base;

    const int nv = g_nv;
    const int ntiles = (nv + 127) >> 7;

    const int srow[4] = { (tid + 0)   >> 3, (tid + 256) >> 3,
                          (tid + 512) >> 3, (tid + 768) >> 3 };
    const int sseg = (tid & 7) * 8;

    // ---- prologue: Q (256 rows) + K0/V0 + mask tail table ----
    #pragma unroll
    for (int it = 0; it < 8; it++) {
        const int idx = tid + it * 256;
        const int r = idx >> 3;
        const int sg = (idx & 7) * 8;
        CP16(sb + QB + (uint32_t)(r * 144 + sg * 2),
             Qg + (size_t)(q0 + r) * RS + sg);
    }
    #pragma unroll
    for (int it = 0; it < 4; it++) {
        const int r = srow[it];
        const uint32_t d = (uint32_t)(r * 144 + sseg * 2);
        CP16(sb + KB + d, Kg + (size_t)r * RS + sseg);
        CP16(sb + VB + d, Vg + (size_t)r * RS + sseg);
    }
    CP_COMMIT();
    #pragma unroll
    for (int it = 0; it < 8; it++) {
        const int idx = tid + it * 256;
        Mh[idx] = (idx < nv) ? __float2half(1.0f) : __float2half(0.0f);
    }
    CP_WAIT0();
    __syncthreads();

    // ---- hoist Q fragments for both sub-blocks ----
    uint32_t qfA[4][4], qfB[4][4];
    {
        const uint32_t qa = sb + QB +
            (uint32_t)(m0 + (mm & 1) * 8 + lr) * 144 + (mm >> 1) * 16;
        #pragma unroll
        for (int kc = 0; kc < 4; kc++) {
            LDSM4(qfA[kc], qa + kc * 32);
            LDSM4(qfB[kc], qa + kc * 32 + 128 * 144);
        }
    }

    const uint32_t kfb = (uint32_t)(lr * 144 + mm * 16);
    const uint32_t vfb = (uint32_t)((mm * 8 + lr) * 144);

    float oA[8][4], oB[8][4];
    #pragma unroll
    for (int nt = 0; nt < 8; nt++)
        #pragma unroll
        for (int e = 0; e < 4; e++) { oA[nt][e] = 0.0f; oB[nt][e] = 0.0f; }
    float olA[4] = {0, 0, 0, 0}, olB[4] = {0, 0, 0, 0};

    // per-tile body; MASKED = 1 only on the final (possibly padded) tile
    #define ATT_TILE(MASKED)                                                    \
        _Pragma("unroll")                                                       \
        for (int p = 0; p < 4; p++) {                                           \
            uint32_t pA[2][4], pB[2][4];                                        \
            _Pragma("unroll")                                                   \
            for (int q2 = 0; q2 < 2; q2++) {                                    \
                _Pragma("unroll")                                               \
                for (int sub = 0; sub < 2; sub++) {                             \
                    const int nt = p * 4 + q2 * 2 + sub;                        \
                    float sA[4] = {0, 0, 0, 0}, sB[4] = {0, 0, 0, 0};           \
                    uint32_t kf0[4], kf1[4];                                    \
                    LDSM4(kf0, kbuf + kfb + nt * 1152);                         \
                    LDSM4(kf1, kbuf + kfb + nt * 1152 + 64);                    \
                    mma16(sA, qfA[0], kf0[0], kf0[1]);                          \
                    mma16(sA, qfA[1], kf0[2], kf0[3]);                          \
                    mma16(sA, qfA[2], kf1[0], kf1[1]);                          \
                    mma16(sA, qfA[3], kf1[2], kf1[3]);                          \
                    mma16(sB, qfB[0], kf0[0], kf0[1]);                          \
                    mma16(sB, qfB[1], kf0[2], kf0[3]);                          \
                    mma16(sB, qfB[2], kf1[0], kf1[1]);                          \
                    mma16(sB, qfB[3], kf1[2], kf1[3]);                          \
                    if (MASKED) {                                               \
                        const uint32_t mk =                                     \
                            *(const uint32_t*)&Mh[j0 + nt * 8 + 2 * c];         \
                        pA[q2][sub * 2] =                                       \
                            hmul2u(ex2h2(packh2(sA[0], sA[1])), mk);            \
                        pA[q2][sub * 2 + 1] =                                   \
                            hmul2u(ex2h2(packh2(sA[2], sA[3])), mk);            \
                        pB[q2][sub * 2] =                                       \
                            hmul2u(ex2h2(packh2(sB[0], sB[1])), mk);            \
                        pB[q2][sub * 2 + 1] =                                   \
                            hmul2u(ex2h2(packh2(sB[2], sB[3])), mk);            \
                    } else {                                                    \
                        pA[q2][sub * 2]     = ex2h2(packh2(sA[0], sA[1]));      \
                        pA[q2][sub * 2 + 1] = ex2h2(packh2(sA[2], sA[3]));      \
                        pB[q2][sub * 2]     = ex2h2(packh2(sB[0], sB[1]));      \
                        pB[q2][sub * 2 + 1] = ex2h2(packh2(sB[2], sB[3]));      \
                    }                                                           \
                }                                                               \
            }                                                                   \
            _Pragma("unroll")                                                   \
            for (int ntd = 0; ntd < 8; ntd++) {                                 \
                uint32_t vf[4];                                                 \
                LDSM4T(vf, vbuf + vfb + p * 4608 + ntd * 16);                   \
                mma16(oA[ntd], pA[0], vf[0], vf[1]);                            \
                mma16(oA[ntd], pA[1], vf[2], vf[3]);                            \
                mma16(oB[ntd], pB[0], vf[0], vf[1]);                            \
                mma16(oB[ntd], pB[1], vf[2], vf[3]);                            \
            }                                                                   \
            /* ones column (row sums): constant B fragment, no LDSM */          \
            mma16(olA, pA[0], ONEH2, ONEH2);                                    \
            mma16(olA, pA[1], ONEH2, ONEH2);                                    \
            mma16(olB, pB[0], ONEH2, ONEH2);                                    \
            mma16(olB, pB[1], ONEH2, ONEH2);                                    \
        }

    #pragma unroll 1
    for (int t = 0; t < ntiles; t++) {
        if (t > 0) { CP_WAIT0(); __syncthreads(); }

        if (t + 1 < ntiles) {
            const int jn = (t + 1) * 128;
            const uint32_t bo = (uint32_t)(((t + 1) & 1) * 18432);
            #pragma unroll
            for (int it = 0; it < 4; it++) {
                const int r = srow[it];
                const uint32_t d = (uint32_t)(r * 144 + sseg * 2);
                CP16(sb + KB + bo + d, Kg + (size_t)(jn + r) * RS + sseg);
                CP16(sb + VB + bo + d, Vg + (size_t)(jn + r) * RS + sseg);
            }
            CP_COMMIT();
        }

        const uint32_t kbuf = sb + KB + (uint32_t)((t & 1) * 18432);
        const uint32_t vbuf = sb + VB + (uint32_t)((t & 1) * 18432);
        const int j0 = t * 128;

        if (t == ntiles - 1) {
            ATT_TILE(1)
        } else {
            ATT_TILE(0)
        }
    }
    #undef ATT_TILE

    const float invA0 = 1.0f / olA[0], invA1 = 1.0f / olA[2];
    const float invB0 = 1.0f / olB[0], invB1 = 1.0f / olB[2];

    const int rA = q0 + m0 + g;
    const int rB = q0 + 128 + m0 + g;
    #pragma unroll
    for (int nt = 0; nt < 8; nt++) {
        const int d = nt * 8 + 2 * c;
        *(float2*)&out[(size_t)rA * RS + base + d] =
            make_float2(oA[nt][0] * invA0, oA[nt][1] * invA0);
        *(float2*)&out[(size_t)(rA + 8) * RS + base + d] =
            make_float2(oA[nt][2] * invA1, oA[nt][3] * invA1);
        *(float2*)&out[(size_t)rB * RS + base + d] =
            make_float2(oB[nt][0] * invB0, oB[nt][1] * invB0);
        *(float2*)&out[(size_t)(rB + 8) * RS + base + d] =
            make_float2(oB[nt][2] * invB1, oB[nt][3] * invB1);
    }
}

// ---------------------------------------------------------------------------
// Launcher. Inputs: query, key, value, mask, w_q, b_q, w_k, b_k, w_v, b_v.
// ---------------------------------------------------------------------------
extern "C" void kernel_launch(void* const* d_in, const int* in_sizes, int n_in,
                              void* d_out, int out_size)
{
    (void)in_sizes; (void)n_in; (void)out_size;
    const float* query = (const float*)d_in[0];
    const float* key_  = (const float*)d_in[1];
    const float* value = (const float*)d_in[2];
    const int*   mask  = (const int*)d_in[3];
    const float* w_q   = (const float*)d_in[4];
    const float* b_q   = (const float*)d_in[5];
    const float* w_k   = (const float*)d_in[6];
    const float* b_k   = (const float*)d_in[7];
    const float* w_v   = (const float*)d_in[8];
    const float* b_v   = (const float*)d_in[9];
    float* out = (float*)d_out;

    static bool attr_done = []() {
        cudaFuncSetAttribute(attn_h,
                             cudaFuncAttributeMaxDynamicSharedMemorySize,
                             ATT_SMEM);
        return true;
    }();
    (void)attr_done;

    scan_mask<<<1, 1024>>>(mask);

    dim3 gprep(S_LEN, 1, 6);
    prep<<<gprep, 256>>>(query, key_, value, w_q, w_k, w_v);

    dim3 gproj(DMODEL / 128, MROWS / 128, 3);   // (8, 32, 3)
    qkv_proj_h<<<gproj, 256>>>(b_q, b_k, b_v);

    dim3 gattn(BATCH * NHEAD, S_LEN / 256, 1);  // (32, 8)
    attn_h<<<gattn, 256, ATT_SMEM>>>(out);
}